// round 10
// baseline (speedup 1.0000x reference)
#include <cuda_runtime.h>
#include <cuda_fp16.h>
#include <math.h>

#define BATCH 4
#define SEQ   2048
#define DM    1024
#define NH    16
#define DH    64
#define MTOT  (BATCH*SEQ)
#define OUT_ELEMS ((size_t)MTOT*DM)

__device__ float g_q[BATCH*NH*SEQ*DH];   // [b,h,s,d]
__device__ float g_k[BATCH*NH*SEQ*DH];
__device__ float g_v[BATCH*NH*SEQ*DH];
__device__ float g_ctx[MTOT*DM];
__device__ float g_fc[MTOT*DM];
__device__ __half g_e[(size_t)BATCH*NH*SEQ*SEQ];   // unnormalized exp(s)/16, fp16

__device__ __forceinline__ unsigned f2tf(float x) {
    unsigned r;
    asm("cvt.rna.tf32.f32 %0, %1;" : "=r"(r) : "f"(x));
    return r;
}

__device__ __forceinline__ void mma8(float* c, const unsigned* a, unsigned b0, unsigned b1) {
    asm volatile(
        "mma.sync.aligned.m16n8k8.row.col.f32.tf32.tf32.f32 "
        "{%0,%1,%2,%3},{%4,%5,%6,%7},{%8,%9},{%0,%1,%2,%3};"
        : "+f"(c[0]), "+f"(c[1]), "+f"(c[2]), "+f"(c[3])
        : "r"(a[0]), "r"(a[1]), "r"(a[2]), "r"(a[3]), "r"(b0), "r"(b1));
}

// ---------------------------------------------------------------------------
// Dense GEMM: C = X[M,K] @ W[N,K]^T, tf32 mma, CTA 128x128, BK=16,
// double-buffered smem with register prefetch.
// mode 0: scatter to [B,H,S,Dh]; mode 1: +residual, row-major.
// ---------------------------------------------------------------------------
#define KPAD 20

__global__ void __launch_bounds__(256, 2)
gemm_tf32(const float* __restrict__ X, const float* __restrict__ W,
          const float* __restrict__ resid, float* __restrict__ Y, int mode)
{
    extern __shared__ unsigned gsm[];
    unsigned (*As)[128][KPAD] = (unsigned(*)[128][KPAD])gsm;
    unsigned (*Bs)[128][KPAD] = (unsigned(*)[128][KPAD])(gsm + 2*128*KPAD);

    const int tid  = threadIdx.x;
    const int lane = tid & 31;
    const int warp = tid >> 5;
    const int warpM = warp >> 1;
    const int warpN = warp & 1;
    const int gid = lane >> 2;
    const int tig = lane & 3;

    const int ms = blockIdx.y * 128;
    const int ns = blockIdx.x * 128;
    const int lr = tid >> 2;
    const int lc = (tid & 3) * 4;

    float acc[2][8][4];
#pragma unroll
    for (int mt = 0; mt < 2; mt++)
#pragma unroll
        for (int nt = 0; nt < 8; nt++)
#pragma unroll
            for (int i = 0; i < 4; i++) acc[mt][nt][i] = 0.f;

    float4 px[2], pw[2];
#pragma unroll
    for (int h = 0; h < 2; h++) {
        int r = lr + h * 64;
        px[h] = *(const float4*)&X[(size_t)(ms + r) * DM + lc];
        pw[h] = *(const float4*)&W[(size_t)(ns + r) * DM + lc];
    }
#pragma unroll
    for (int h = 0; h < 2; h++) {
        int r = lr + h * 64;
        As[0][r][lc+0] = f2tf(px[h].x); As[0][r][lc+1] = f2tf(px[h].y);
        As[0][r][lc+2] = f2tf(px[h].z); As[0][r][lc+3] = f2tf(px[h].w);
        Bs[0][r][lc+0] = f2tf(pw[h].x); Bs[0][r][lc+1] = f2tf(pw[h].y);
        Bs[0][r][lc+2] = f2tf(pw[h].z); Bs[0][r][lc+3] = f2tf(pw[h].w);
    }
    __syncthreads();

    int buf = 0;
    for (int k0 = 0; k0 < DM; k0 += 16, buf ^= 1) {
        float4 nx[2], nw[2];
        const bool more = (k0 + 16 < DM);
        if (more) {
#pragma unroll
            for (int h = 0; h < 2; h++) {
                int r = lr + h * 64;
                nx[h] = *(const float4*)&X[(size_t)(ms + r) * DM + k0 + 16 + lc];
                nw[h] = *(const float4*)&W[(size_t)(ns + r) * DM + k0 + 16 + lc];
            }
        }

#pragma unroll
        for (int ks = 0; ks < 2; ks++) {
            const int kc = ks * 8 + tig;
            unsigned a[2][4];
#pragma unroll
            for (int mt = 0; mt < 2; mt++) {
                int base = warpM * 32 + mt * 16;
                a[mt][0] = As[buf][base + gid][kc];
                a[mt][1] = As[buf][base + gid + 8][kc];
                a[mt][2] = As[buf][base + gid][kc + 4];
                a[mt][3] = As[buf][base + gid + 8][kc + 4];
            }
#pragma unroll
            for (int nt = 0; nt < 8; nt++) {
                int cb = warpN * 64 + nt * 8 + gid;
                unsigned b0 = Bs[buf][cb][kc];
                unsigned b1 = Bs[buf][cb][kc + 4];
                mma8(acc[0][nt], a[0], b0, b1);
                mma8(acc[1][nt], a[1], b0, b1);
            }
        }

        if (more) {
            int nb = buf ^ 1;
#pragma unroll
            for (int h = 0; h < 2; h++) {
                int r = lr + h * 64;
                As[nb][r][lc+0] = f2tf(nx[h].x); As[nb][r][lc+1] = f2tf(nx[h].y);
                As[nb][r][lc+2] = f2tf(nx[h].z); As[nb][r][lc+3] = f2tf(nx[h].w);
                Bs[nb][r][lc+0] = f2tf(nw[h].x); Bs[nb][r][lc+1] = f2tf(nw[h].y);
                Bs[nb][r][lc+2] = f2tf(nw[h].z); Bs[nb][r][lc+3] = f2tf(nw[h].w);
            }
        }
        __syncthreads();
    }

#pragma unroll
    for (int mt = 0; mt < 2; mt++) {
#pragma unroll
        for (int nt = 0; nt < 8; nt++) {
#pragma unroll
            for (int i = 0; i < 4; i++) {
                int m = ms + warpM * 32 + mt * 16 + gid + (i >> 1) * 8;
                int n = ns + warpN * 64 + nt * 8 + tig * 2 + (i & 1);
                float v = acc[mt][nt][i];
                if (mode == 0) {
                    int b_ = m >> 11, s_ = m & 2047;
                    int h = n >> 6, dh = n & 63;
                    Y[(((size_t)(b_*NH + h))*SEQ + s_)*DH + dh] = v;
                } else {
                    Y[(size_t)m * DM + n] = v + resid[(size_t)m * DM + n];
                }
            }
        }
    }
}

// ---------------------------------------------------------------------------
// Flash-style attention, single compute pass. CTA = (b,h, 64 q rows), 256 thr,
// 8 warps = 4 q-groups x 2 key-slices. exp() without max-subtraction (scores
// bounded). Per 128-key tile: QK mma (Q hi/lo tf32) -> e=exp(s) -> row sums +
// fp16 e -> g_e + e->smem roundtrip -> PV mma. Then reduce sums/O, and a
// normalization sweep reads g_e (L2-hot) and writes p = e*inv to gmem attn.
// ---------------------------------------------------------------------------
#define AKT   128
#define NTIL  (SEQ/AKT)
#define SKSTR 68
#define SVSTR 72
#define SESTR 68
#define SM_K   0
#define SM_V   (AKT*SKSTR)                 // 8704
#define SM_E   (SM_V + AKT*SVSTR)          // 17920
#define SM_SUM (SM_E + 8*16*SESTR)         // 26624
#define SM_INV (SM_SUM + 128)              // 26752
#define SM_ATT (SM_INV + 64)               // 26816 floats = 107264 B

__global__ void __launch_bounds__(256, 2)
attn_kernel(const float* __restrict__ gq, const float* __restrict__ gk,
            const float* __restrict__ gv, float* __restrict__ attn_out,
            float* __restrict__ ctx, __half* __restrict__ gE)
{
    extern __shared__ float sm[];
    float* sK   = sm + SM_K;
    float* sV   = sm + SM_V;
    float* sE   = sm + SM_E;
    float* sSum = sm + SM_SUM;
    float* sInv = sm + SM_INV;

    const int tid  = threadIdx.x;
    const int lane = tid & 31;
    const int w    = tid >> 5;       // 0..7
    const int gid  = lane >> 2;      // 0..7
    const int tig  = lane & 3;       // 0..3
    const int qg   = w >> 1;         // 0..3
    const int ns   = w & 1;          // 0..1

    const int bid = blockIdx.x;
    const int qt  = bid & 31;
    const int bh  = bid >> 5;
    const int q0  = qt * 64;

    const float* Qb = gq + (size_t)bh * SEQ * DH;
    const float* Kb = gk + (size_t)bh * SEQ * DH;
    const float* Vb = gv + (size_t)bh * SEQ * DH;

    float* sEw = sE + w * 16 * SESTR;
    const int row0 = q0 + qg*16 + gid;
    __half* eRow0 = gE + ((size_t)bh*SEQ + row0)*SEQ;
    __half* eRow1 = eRow0 + (size_t)8*SEQ;

    // ---- Q fragments (hi/lo tf32), scale folded ----
    unsigned qhi[8][4], qlo[8][4];
    {
        const float* Qr0 = Qb + (size_t)(q0 + qg*16 + gid) * DH;
        const float* Qr1 = Qr0 + (size_t)8 * DH;
#pragma unroll
        for (int kc = 0; kc < 8; kc++) {
            float v[4];
            v[0] = Qr0[kc*8 + tig]     * 0.125f;
            v[1] = Qr1[kc*8 + tig]     * 0.125f;
            v[2] = Qr0[kc*8 + tig + 4] * 0.125f;
            v[3] = Qr1[kc*8 + tig + 4] * 0.125f;
#pragma unroll
            for (int i = 0; i < 4; i++) {
                unsigned h = f2tf(v[i]);
                qhi[kc][i] = h;
                qlo[kc][i] = f2tf(v[i] - __uint_as_float(h));
            }
        }
    }

    float rsum0 = 0.f, rsum1 = 0.f;
    float acc2[8][4];
#pragma unroll
    for (int nd = 0; nd < 8; nd++)
#pragma unroll
        for (int i = 0; i < 4; i++) acc2[nd][i] = 0.f;

    // ================= main pass =================
    for (int t = 0; t < NTIL; t++) {
        __syncthreads();
#pragma unroll
        for (int i = 0; i < 8; i++) {
            int fidx = tid + i * 256;            // 0..2047
            int r = fidx >> 4, c4 = (fidx & 15) << 2;
            float4 kv = *(const float4*)&Kb[(size_t)(t*AKT + r)*DH + c4];
            float* d = &sK[r*SKSTR + c4];
            d[0] = __uint_as_float(f2tf(kv.x));
            d[1] = __uint_as_float(f2tf(kv.y));
            d[2] = __uint_as_float(f2tf(kv.z));
            d[3] = __uint_as_float(f2tf(kv.w));
            float4 vv = *(const float4*)&Vb[(size_t)(t*AKT + r)*DH + c4];
            float* e = &sV[r*SVSTR + c4];
            e[0] = __uint_as_float(f2tf(vv.x));
            e[1] = __uint_as_float(f2tf(vv.y));
            e[2] = __uint_as_float(f2tf(vv.z));
            e[3] = __uint_as_float(f2tf(vv.w));
        }
        __syncthreads();

        // QK + exp + staging (warp-local), fp16 e -> gmem (scaled by 1/16)
#pragma unroll
        for (int n8 = 0; n8 < 8; n8++) {
            const int n0 = ns * 64 + n8 * 8;
            float a[4] = {0.f, 0.f, 0.f, 0.f};
#pragma unroll
            for (int kc = 0; kc < 8; kc++) {
                unsigned b0 = __float_as_uint(sK[(n0 + gid)*SKSTR + kc*8 + tig]);
                unsigned b1 = __float_as_uint(sK[(n0 + gid)*SKSTR + kc*8 + tig + 4]);
                mma8(a, qhi[kc], b0, b1);
                mma8(a, qlo[kc], b0, b1);
            }
            a[0] = __expf(a[0]); a[1] = __expf(a[1]);
            a[2] = __expf(a[2]); a[3] = __expf(a[3]);
            rsum0 += a[0] + a[1];
            rsum1 += a[2] + a[3];
            const int col = t*AKT + n0 + 2*tig;
            *(__half2*)&eRow0[col] = __floats2half2_rn(a[0]*0.0625f, a[1]*0.0625f);
            *(__half2*)&eRow1[col] = __floats2half2_rn(a[2]*0.0625f, a[3]*0.0625f);
            sEw[gid*SESTR + n8*8 + 2*tig]       = __uint_as_float(f2tf(a[0]));
            sEw[gid*SESTR + n8*8 + 2*tig + 1]   = __uint_as_float(f2tf(a[1]));
            sEw[(gid+8)*SESTR + n8*8 + 2*tig]   = __uint_as_float(f2tf(a[2]));
            sEw[(gid+8)*SESTR + n8*8 + 2*tig+1] = __uint_as_float(f2tf(a[3]));
        }
        __syncwarp();

        // PV over this warp's 64 keys
#pragma unroll
        for (int k8 = 0; k8 < 8; k8++) {
            unsigned a[4];
            a[0] = __float_as_uint(sEw[gid*SESTR + k8*8 + tig]);
            a[1] = __float_as_uint(sEw[(gid+8)*SESTR + k8*8 + tig]);
            a[2] = __float_as_uint(sEw[gid*SESTR + k8*8 + tig + 4]);
            a[3] = __float_as_uint(sEw[(gid+8)*SESTR + k8*8 + tig + 4]);
            const int kr = ns * 64 + k8 * 8;
#pragma unroll
            for (int nd = 0; nd < 8; nd++) {
                unsigned b0 = __float_as_uint(sV[(kr + tig)*SVSTR + nd*8 + gid]);
                unsigned b1 = __float_as_uint(sV[(kr + tig + 4)*SVSTR + nd*8 + gid]);
                mma8(acc2[nd], a, b0, b1);
            }
        }
    }

    // ---- row-sum reduction ----
    rsum0 += __shfl_xor_sync(0xffffffffu, rsum0, 1);
    rsum0 += __shfl_xor_sync(0xffffffffu, rsum0, 2);
    rsum1 += __shfl_xor_sync(0xffffffffu, rsum1, 1);
    rsum1 += __shfl_xor_sync(0xffffffffu, rsum1, 2);
    if (tig == 0) {
        sSum[w*16 + gid]     = rsum0;
        sSum[w*16 + gid + 8] = rsum1;
    }
    __syncthreads();
    if (tid < 64) {
        int qgq = tid >> 4, r = tid & 15;
        float s = sSum[(qgq*2)*16 + r] + sSum[(qgq*2 + 1)*16 + r];
        sInv[tid] = 1.f / s;
    }
    // ---- O partial stage (reuse sE) ----
#pragma unroll
    for (int nd = 0; nd < 8; nd++) {
        sEw[gid*SESTR + nd*8 + 2*tig]       = acc2[nd][0];
        sEw[gid*SESTR + nd*8 + 2*tig + 1]   = acc2[nd][1];
        sEw[(gid+8)*SESTR + nd*8 + 2*tig]   = acc2[nd][2];
        sEw[(gid+8)*SESTR + nd*8 + 2*tig+1] = acc2[nd][3];
    }
    __syncthreads();

    // ---- ctx write ----
    {
        const int b_ = bh >> 4, h = bh & 15;
#pragma unroll
        for (int i = 0; i < 16; i++) {
            int idx = tid + i * 256;             // 0..4095
            int q = idx >> 6, dh = idx & 63;
            int qgi = q >> 4, r = q & 15;
            float o = sE[(qgi*2)*16*SESTR + r*SESTR + dh]
                    + sE[(qgi*2 + 1)*16*SESTR + r*SESTR + dh];
            o *= sInv[q];
            ctx[((size_t)(b_*SEQ + q0 + q))*DM + h*DH + dh] = o;
        }
    }

    // ---- normalization sweep: p = e_fp16 * (inv*16) -> gmem attn ----
    {
        const uint2* src = (const uint2*)(gE + ((size_t)bh*SEQ + q0)*SEQ);
        float* dst = attn_out + ((size_t)bh*SEQ + q0)*SEQ;
#pragma unroll 4
        for (int i = tid; i < 64*SEQ/4; i += 256) {
            float inv = sInv[i >> 9] * 16.f;     // (i*4) >> 11
            uint2 raw = src[i];
            float2 f0 = __half22float2(*(const __half2*)&raw.x);
            float2 f1 = __half22float2(*(const __half2*)&raw.y);
            float4 p = make_float4(f0.x*inv, f0.y*inv, f1.x*inv, f1.y*inv);
            *(float4*)&dst[i*4] = p;
        }
    }
}

// ---------------------------------------------------------------------------
__global__ void ln_kernel(const float* __restrict__ x, float* __restrict__ out)
{
    __shared__ float red[16];
    const int row = blockIdx.x, tid = threadIdx.x;
    const float* xr = x + (size_t)row * DM;
    float4 d = ((const float4*)xr)[tid];
    float s  = d.x + d.y + d.z + d.w;
    float sq = d.x*d.x + d.y*d.y + d.z*d.z + d.w*d.w;
#pragma unroll
    for (int o = 16; o; o >>= 1) {
        s  += __shfl_xor_sync(0xffffffffu, s,  o);
        sq += __shfl_xor_sync(0xffffffffu, sq, o);
    }
    int warp = tid >> 5, lane = tid & 31;
    if (lane == 0) { red[warp] = s; red[warp + 8] = sq; }
    __syncthreads();
    float st = 0.f, sqt = 0.f;
#pragma unroll
    for (int i = 0; i < 8; i++) { st += red[i]; sqt += red[8 + i]; }
    float mean = st * (1.f/1024.f);
    float var  = sqt * (1.f/1024.f) - mean * mean;
    float rstd = rsqrtf(var + 1e-5f);
    float4 o;
    o.x = (d.x - mean) * rstd; o.y = (d.y - mean) * rstd;
    o.z = (d.z - mean) * rstd; o.w = (d.w - mean) * rstd;
    ((float4*)(out + (size_t)row * DM))[tid] = o;
}

// ---------------------------------------------------------------------------
extern "C" void kernel_launch(void* const* d_in, const int* in_sizes, int n_in,
                              void* d_out, int out_size)
{
    const float* iq  = (const float*)d_in[0];
    const float* ik  = (const float*)d_in[1];
    const float* iv  = (const float*)d_in[2];
    const float* wq  = (const float*)d_in[3];
    const float* wk  = (const float*)d_in[4];
    const float* wv  = (const float*)d_in[5];
    const float* wfc = (const float*)d_in[6];

    float* out  = (float*)d_out;
    float* attn = out + OUT_ELEMS;

    float *gq, *gk, *gv, *gctx, *gfc;
    __half* ge;
    cudaGetSymbolAddress((void**)&gq,   g_q);
    cudaGetSymbolAddress((void**)&gk,   g_k);
    cudaGetSymbolAddress((void**)&gv,   g_v);
    cudaGetSymbolAddress((void**)&gctx, g_ctx);
    cudaGetSymbolAddress((void**)&gfc,  g_fc);
    cudaGetSymbolAddress((void**)&ge,   g_e);

    dim3 gg(DM/128, MTOT/128);
    size_t gemm_smem = (size_t)4 * 128 * KPAD * sizeof(unsigned);
    cudaFuncSetAttribute(gemm_tf32, cudaFuncAttributeMaxDynamicSharedMemorySize, (int)gemm_smem);

    gemm_tf32<<<gg, 256, gemm_smem>>>(iq, wq, nullptr, gq, 0);
    gemm_tf32<<<gg, 256, gemm_smem>>>(ik, wk, nullptr, gk, 0);
    gemm_tf32<<<gg, 256, gemm_smem>>>(iv, wv, nullptr, gv, 0);

    size_t smem = (size_t)SM_ATT * sizeof(float);   // 107264 B
    cudaFuncSetAttribute(attn_kernel, cudaFuncAttributeMaxDynamicSharedMemorySize, (int)smem);
    attn_kernel<<<BATCH*NH*(SEQ/64), 256, smem>>>(gq, gk, gv, attn, gctx, ge);

    gemm_tf32<<<gg, 256, gemm_smem>>>(gctx, wfc, iq, gfc, 1);
    ln_kernel<<<MTOT, 256>>>(gfc, out);
}

// round 11
// speedup vs baseline: 1.0812x; 1.0812x over previous
#include <cuda_runtime.h>
#include <cuda_fp16.h>
#include <math.h>

#define BATCH 4
#define SEQ   2048
#define DM    1024
#define NH    16
#define DH    64
#define MTOT  (BATCH*SEQ)
#define OUT_ELEMS ((size_t)MTOT*DM)

__device__ float g_q[BATCH*NH*SEQ*DH];   // [b,h,s,d]
__device__ float g_k[BATCH*NH*SEQ*DH];
__device__ float g_v[BATCH*NH*SEQ*DH];
__device__ float g_ctx[MTOT*DM];
__device__ float g_fc[MTOT*DM];
__device__ __half g_e[(size_t)BATCH*NH*SEQ*SEQ];   // unnormalized exp(s)/16, fp16

__device__ __forceinline__ unsigned f2tf(float x) {
    unsigned r;
    asm("cvt.rna.tf32.f32 %0, %1;" : "=r"(r) : "f"(x));
    return r;
}

__device__ __forceinline__ void mma8(float* c, const unsigned* a, unsigned b0, unsigned b1) {
    asm volatile(
        "mma.sync.aligned.m16n8k8.row.col.f32.tf32.tf32.f32 "
        "{%0,%1,%2,%3},{%4,%5,%6,%7},{%8,%9},{%0,%1,%2,%3};"
        : "+f"(c[0]), "+f"(c[1]), "+f"(c[2]), "+f"(c[3])
        : "r"(a[0]), "r"(a[1]), "r"(a[2]), "r"(a[3]), "r"(b0), "r"(b1));
}

// ---------------------------------------------------------------------------
// Dense GEMM: C = X[M,K] @ W[N,K]^T, tf32 mma, CTA 128x128, BK=16,
// double-buffered smem with register prefetch.
// mode 0: scatter to [B,H,S,Dh]; mode 1: +residual, row-major.
// ---------------------------------------------------------------------------
#define KPAD 20

__global__ void __launch_bounds__(256, 2)
gemm_tf32(const float* __restrict__ X, const float* __restrict__ W,
          const float* __restrict__ resid, float* __restrict__ Y, int mode)
{
    extern __shared__ unsigned gsm[];
    unsigned (*As)[128][KPAD] = (unsigned(*)[128][KPAD])gsm;
    unsigned (*Bs)[128][KPAD] = (unsigned(*)[128][KPAD])(gsm + 2*128*KPAD);

    const int tid  = threadIdx.x;
    const int lane = tid & 31;
    const int warp = tid >> 5;
    const int warpM = warp >> 1;
    const int warpN = warp & 1;
    const int gid = lane >> 2;
    const int tig = lane & 3;

    const int ms = blockIdx.y * 128;
    const int ns = blockIdx.x * 128;
    const int lr = tid >> 2;
    const int lc = (tid & 3) * 4;

    float acc[2][8][4];
#pragma unroll
    for (int mt = 0; mt < 2; mt++)
#pragma unroll
        for (int nt = 0; nt < 8; nt++)
#pragma unroll
            for (int i = 0; i < 4; i++) acc[mt][nt][i] = 0.f;

    float4 px[2], pw[2];
#pragma unroll
    for (int h = 0; h < 2; h++) {
        int r = lr + h * 64;
        px[h] = *(const float4*)&X[(size_t)(ms + r) * DM + lc];
        pw[h] = *(const float4*)&W[(size_t)(ns + r) * DM + lc];
    }
#pragma unroll
    for (int h = 0; h < 2; h++) {
        int r = lr + h * 64;
        As[0][r][lc+0] = f2tf(px[h].x); As[0][r][lc+1] = f2tf(px[h].y);
        As[0][r][lc+2] = f2tf(px[h].z); As[0][r][lc+3] = f2tf(px[h].w);
        Bs[0][r][lc+0] = f2tf(pw[h].x); Bs[0][r][lc+1] = f2tf(pw[h].y);
        Bs[0][r][lc+2] = f2tf(pw[h].z); Bs[0][r][lc+3] = f2tf(pw[h].w);
    }
    __syncthreads();

    int buf = 0;
    for (int k0 = 0; k0 < DM; k0 += 16, buf ^= 1) {
        float4 nx[2], nw[2];
        const bool more = (k0 + 16 < DM);
        if (more) {
#pragma unroll
            for (int h = 0; h < 2; h++) {
                int r = lr + h * 64;
                nx[h] = *(const float4*)&X[(size_t)(ms + r) * DM + k0 + 16 + lc];
                nw[h] = *(const float4*)&W[(size_t)(ns + r) * DM + k0 + 16 + lc];
            }
        }

#pragma unroll
        for (int ks = 0; ks < 2; ks++) {
            const int kc = ks * 8 + tig;
            unsigned a[2][4];
#pragma unroll
            for (int mt = 0; mt < 2; mt++) {
                int base = warpM * 32 + mt * 16;
                a[mt][0] = As[buf][base + gid][kc];
                a[mt][1] = As[buf][base + gid + 8][kc];
                a[mt][2] = As[buf][base + gid][kc + 4];
                a[mt][3] = As[buf][base + gid + 8][kc + 4];
            }
#pragma unroll
            for (int nt = 0; nt < 8; nt++) {
                int cb = warpN * 64 + nt * 8 + gid;
                unsigned b0 = Bs[buf][cb][kc];
                unsigned b1 = Bs[buf][cb][kc + 4];
                mma8(acc[0][nt], a[0], b0, b1);
                mma8(acc[1][nt], a[1], b0, b1);
            }
        }

        if (more) {
            int nb = buf ^ 1;
#pragma unroll
            for (int h = 0; h < 2; h++) {
                int r = lr + h * 64;
                As[nb][r][lc+0] = f2tf(nx[h].x); As[nb][r][lc+1] = f2tf(nx[h].y);
                As[nb][r][lc+2] = f2tf(nx[h].z); As[nb][r][lc+3] = f2tf(nx[h].w);
                Bs[nb][r][lc+0] = f2tf(nw[h].x); Bs[nb][r][lc+1] = f2tf(nw[h].y);
                Bs[nb][r][lc+2] = f2tf(nw[h].z); Bs[nb][r][lc+3] = f2tf(nw[h].w);
            }
        }
        __syncthreads();
    }

#pragma unroll
    for (int mt = 0; mt < 2; mt++) {
#pragma unroll
        for (int nt = 0; nt < 8; nt++) {
#pragma unroll
            for (int i = 0; i < 4; i++) {
                int m = ms + warpM * 32 + mt * 16 + gid + (i >> 1) * 8;
                int n = ns + warpN * 64 + nt * 8 + tig * 2 + (i & 1);
                float v = acc[mt][nt][i];
                if (mode == 0) {
                    int b_ = m >> 11, s_ = m & 2047;
                    int h = n >> 6, dh = n & 63;
                    Y[(((size_t)(b_*NH + h))*SEQ + s_)*DH + dh] = v;
                } else {
                    Y[(size_t)m * DM + n] = v + resid[(size_t)m * DM + n];
                }
            }
        }
    }
}

// ---------------------------------------------------------------------------
// Flash-style attention, single compute pass. CTA = (b,h, 64 q rows), 256 thr,
// 8 warps = 4 q-groups x 2 key-slices. exp() without max-subtraction (scores
// bounded). Per 128-key tile: QK mma (Q hi/lo tf32) -> e=exp(s) -> row sums +
// e->smem roundtrip -> PV mma -> coalesced fp16 e dump (from smem, post-PV).
// Then reduce sums/O, write ctx, and a normalization sweep reads the CTA's
// own fp16 block (L2-hot) and writes p = e*inv to gmem attn.
// ---------------------------------------------------------------------------
#define AKT   128
#define NTIL  (SEQ/AKT)
#define SKSTR 68
#define SVSTR 72
#define SESTR 68
#define SM_K   0
#define SM_V   (AKT*SKSTR)                 // 8704
#define SM_E   (SM_V + AKT*SVSTR)          // 17920
#define SM_SUM (SM_E + 8*16*SESTR)         // 26624
#define SM_INV (SM_SUM + 128)              // 26752
#define SM_ATT (SM_INV + 64)               // 26816 floats = 107264 B

__global__ void __launch_bounds__(256, 2)
attn_kernel(const float* __restrict__ gq, const float* __restrict__ gk,
            const float* __restrict__ gv, float* __restrict__ attn_out,
            float* __restrict__ ctx, __half* __restrict__ gE)
{
    extern __shared__ float sm[];
    float* sK   = sm + SM_K;
    float* sV   = sm + SM_V;
    float* sE   = sm + SM_E;
    float* sSum = sm + SM_SUM;
    float* sInv = sm + SM_INV;

    const int tid  = threadIdx.x;
    const int lane = tid & 31;
    const int w    = tid >> 5;       // 0..7
    const int gid  = lane >> 2;      // 0..7
    const int tig  = lane & 3;       // 0..3
    const int qg   = w >> 1;         // 0..3
    const int ns   = w & 1;          // 0..1

    const int bid = blockIdx.x;
    const int qt  = bid & 31;
    const int bh  = bid >> 5;
    const int q0  = qt * 64;

    const float* Qb = gq + (size_t)bh * SEQ * DH;
    const float* Kb = gk + (size_t)bh * SEQ * DH;
    const float* Vb = gv + (size_t)bh * SEQ * DH;

    float* sEw = sE + w * 16 * SESTR;

    // ---- Q fragments (hi/lo tf32), scale folded ----
    unsigned qhi[8][4], qlo[8][4];
    {
        const float* Qr0 = Qb + (size_t)(q0 + qg*16 + gid) * DH;
        const float* Qr1 = Qr0 + (size_t)8 * DH;
#pragma unroll
        for (int kc = 0; kc < 8; kc++) {
            float v[4];
            v[0] = Qr0[kc*8 + tig]     * 0.125f;
            v[1] = Qr1[kc*8 + tig]     * 0.125f;
            v[2] = Qr0[kc*8 + tig + 4] * 0.125f;
            v[3] = Qr1[kc*8 + tig + 4] * 0.125f;
#pragma unroll
            for (int i = 0; i < 4; i++) {
                unsigned h = f2tf(v[i]);
                qhi[kc][i] = h;
                qlo[kc][i] = f2tf(v[i] - __uint_as_float(h));
            }
        }
    }

    float rsum0 = 0.f, rsum1 = 0.f;
    float acc2[8][4];
#pragma unroll
    for (int nd = 0; nd < 8; nd++)
#pragma unroll
        for (int i = 0; i < 4; i++) acc2[nd][i] = 0.f;

    // ================= main pass =================
    for (int t = 0; t < NTIL; t++) {
        __syncthreads();
#pragma unroll
        for (int i = 0; i < 8; i++) {
            int fidx = tid + i * 256;            // 0..2047
            int r = fidx >> 4, c4 = (fidx & 15) << 2;
            float4 kv = *(const float4*)&Kb[(size_t)(t*AKT + r)*DH + c4];
            float* d = &sK[r*SKSTR + c4];
            d[0] = __uint_as_float(f2tf(kv.x));
            d[1] = __uint_as_float(f2tf(kv.y));
            d[2] = __uint_as_float(f2tf(kv.z));
            d[3] = __uint_as_float(f2tf(kv.w));
            float4 vv = *(const float4*)&Vb[(size_t)(t*AKT + r)*DH + c4];
            float* e = &sV[r*SVSTR + c4];
            e[0] = __uint_as_float(f2tf(vv.x));
            e[1] = __uint_as_float(f2tf(vv.y));
            e[2] = __uint_as_float(f2tf(vv.z));
            e[3] = __uint_as_float(f2tf(vv.w));
        }
        __syncthreads();

        // QK + exp + e staging (warp-local)
#pragma unroll
        for (int n8 = 0; n8 < 8; n8++) {
            const int n0 = ns * 64 + n8 * 8;
            float a[4] = {0.f, 0.f, 0.f, 0.f};
#pragma unroll
            for (int kc = 0; kc < 8; kc++) {
                unsigned b0 = __float_as_uint(sK[(n0 + gid)*SKSTR + kc*8 + tig]);
                unsigned b1 = __float_as_uint(sK[(n0 + gid)*SKSTR + kc*8 + tig + 4]);
                mma8(a, qhi[kc], b0, b1);
                mma8(a, qlo[kc], b0, b1);
            }
            a[0] = __expf(a[0]); a[1] = __expf(a[1]);
            a[2] = __expf(a[2]); a[3] = __expf(a[3]);
            rsum0 += a[0] + a[1];
            rsum1 += a[2] + a[3];
            sEw[gid*SESTR + n8*8 + 2*tig]       = __uint_as_float(f2tf(a[0]));
            sEw[gid*SESTR + n8*8 + 2*tig + 1]   = __uint_as_float(f2tf(a[1]));
            sEw[(gid+8)*SESTR + n8*8 + 2*tig]   = __uint_as_float(f2tf(a[2]));
            sEw[(gid+8)*SESTR + n8*8 + 2*tig+1] = __uint_as_float(f2tf(a[3]));
        }
        __syncwarp();

        // PV over this warp's 64 keys
#pragma unroll
        for (int k8 = 0; k8 < 8; k8++) {
            unsigned a[4];
            a[0] = __float_as_uint(sEw[gid*SESTR + k8*8 + tig]);
            a[1] = __float_as_uint(sEw[(gid+8)*SESTR + k8*8 + tig]);
            a[2] = __float_as_uint(sEw[gid*SESTR + k8*8 + tig + 4]);
            a[3] = __float_as_uint(sEw[(gid+8)*SESTR + k8*8 + tig + 4]);
            const int kr = ns * 64 + k8 * 8;
#pragma unroll
            for (int nd = 0; nd < 8; nd++) {
                unsigned b0 = __float_as_uint(sV[(kr + tig)*SVSTR + nd*8 + gid]);
                unsigned b1 = __float_as_uint(sV[(kr + tig + 4)*SVSTR + nd*8 + gid]);
                mma8(acc2[nd], a, b0, b1);
            }
        }

        // e dump: sEw (16x64) -> gE fp16 (scaled 1/16), coalesced 64B segments
        {
            const int r  = lane >> 2;            // 0..7
            const int cq = (lane & 3) * 8;       // halves 0,8,16,24 -> bytes 0..48
#pragma unroll
            for (int rg = 0; rg < 16; rg += 8) {
#pragma unroll
                for (int cp = 0; cp < 64; cp += 32) {
                    const float* s = &sEw[(r + rg)*SESTR + cq + cp];
                    float4 v0 = *(const float4*)&s[0];
                    float4 v1 = *(const float4*)&s[4];
                    __half2 h0 = __floats2half2_rn(v0.x*0.0625f, v0.y*0.0625f);
                    __half2 h1 = __floats2half2_rn(v0.z*0.0625f, v0.w*0.0625f);
                    __half2 h2 = __floats2half2_rn(v1.x*0.0625f, v1.y*0.0625f);
                    __half2 h3 = __floats2half2_rn(v1.z*0.0625f, v1.w*0.0625f);
                    uint4 pk;
                    pk.x = *(const unsigned*)&h0;
                    pk.y = *(const unsigned*)&h1;
                    pk.z = *(const unsigned*)&h2;
                    pk.w = *(const unsigned*)&h3;
                    *(uint4*)&gE[((size_t)bh*SEQ + q0 + qg*16 + rg + r)*SEQ
                                 + t*AKT + ns*64 + cq + cp] = pk;
                }
            }
        }
    }

    // ---- row-sum reduction ----
    rsum0 += __shfl_xor_sync(0xffffffffu, rsum0, 1);
    rsum0 += __shfl_xor_sync(0xffffffffu, rsum0, 2);
    rsum1 += __shfl_xor_sync(0xffffffffu, rsum1, 1);
    rsum1 += __shfl_xor_sync(0xffffffffu, rsum1, 2);
    if (tig == 0) {
        sSum[w*16 + gid]     = rsum0;
        sSum[w*16 + gid + 8] = rsum1;
    }
    __syncthreads();
    if (tid < 64) {
        int qgq = tid >> 4, r = tid & 15;
        float s = sSum[(qgq*2)*16 + r] + sSum[(qgq*2 + 1)*16 + r];
        sInv[tid] = 1.f / s;
    }
    // ---- O partial stage (reuse sE) ----
#pragma unroll
    for (int nd = 0; nd < 8; nd++) {
        sEw[gid*SESTR + nd*8 + 2*tig]       = acc2[nd][0];
        sEw[gid*SESTR + nd*8 + 2*tig + 1]   = acc2[nd][1];
        sEw[(gid+8)*SESTR + nd*8 + 2*tig]   = acc2[nd][2];
        sEw[(gid+8)*SESTR + nd*8 + 2*tig+1] = acc2[nd][3];
    }
    __syncthreads();

    // ---- ctx write ----
    {
        const int b_ = bh >> 4, h = bh & 15;
#pragma unroll
        for (int i = 0; i < 16; i++) {
            int idx = tid + i * 256;             // 0..4095
            int q = idx >> 6, dh = idx & 63;
            int qgi = q >> 4, r = q & 15;
            float o = sE[(qgi*2)*16*SESTR + r*SESTR + dh]
                    + sE[(qgi*2 + 1)*16*SESTR + r*SESTR + dh];
            o *= sInv[q];
            ctx[((size_t)(b_*SEQ + q0 + q))*DM + h*DH + dh] = o;
        }
    }

    // ---- normalization sweep: p = e_fp16 * (inv*16) -> gmem attn ----
    {
        const uint4* src = (const uint4*)(gE + ((size_t)bh*SEQ + q0)*SEQ);
        float* dst = attn_out + ((size_t)bh*SEQ + q0)*SEQ;
#pragma unroll 4
        for (int i = tid; i < 64*SEQ/8; i += 256) {   // 16384 uint4
            float inv = sInv[i >> 8] * 16.f;           // (i*8) >> 11
            uint4 raw = src[i];
            float2 f0 = __half22float2(*(const __half2*)&raw.x);
            float2 f1 = __half22float2(*(const __half2*)&raw.y);
            float2 f2 = __half22float2(*(const __half2*)&raw.z);
            float2 f3 = __half22float2(*(const __half2*)&raw.w);
            float4 p0 = make_float4(f0.x*inv, f0.y*inv, f1.x*inv, f1.y*inv);
            float4 p1 = make_float4(f2.x*inv, f2.y*inv, f3.x*inv, f3.y*inv);
            *(float4*)&dst[i*8]     = p0;
            *(float4*)&dst[i*8 + 4] = p1;
        }
    }
}

// ---------------------------------------------------------------------------
__global__ void ln_kernel(const float* __restrict__ x, float* __restrict__ out)
{
    __shared__ float red[16];
    const int row = blockIdx.x, tid = threadIdx.x;
    const float* xr = x + (size_t)row * DM;
    float4 d = ((const float4*)xr)[tid];
    float s  = d.x + d.y + d.z + d.w;
    float sq = d.x*d.x + d.y*d.y + d.z*d.z + d.w*d.w;
#pragma unroll
    for (int o = 16; o; o >>= 1) {
        s  += __shfl_xor_sync(0xffffffffu, s,  o);
        sq += __shfl_xor_sync(0xffffffffu, sq, o);
    }
    int warp = tid >> 5, lane = tid & 31;
    if (lane == 0) { red[warp] = s; red[warp + 8] = sq; }
    __syncthreads();
    float st = 0.f, sqt = 0.f;
#pragma unroll
    for (int i = 0; i < 8; i++) { st += red[i]; sqt += red[8 + i]; }
    float mean = st * (1.f/1024.f);
    float var  = sqt * (1.f/1024.f) - mean * mean;
    float rstd = rsqrtf(var + 1e-5f);
    float4 o;
    o.x = (d.x - mean) * rstd; o.y = (d.y - mean) * rstd;
    o.z = (d.z - mean) * rstd; o.w = (d.w - mean) * rstd;
    ((float4*)(out + (size_t)row * DM))[tid] = o;
}

// ---------------------------------------------------------------------------
extern "C" void kernel_launch(void* const* d_in, const int* in_sizes, int n_in,
                              void* d_out, int out_size)
{
    const float* iq  = (const float*)d_in[0];
    const float* ik  = (const float*)d_in[1];
    const float* iv  = (const float*)d_in[2];
    const float* wq  = (const float*)d_in[3];
    const float* wk  = (const float*)d_in[4];
    const float* wv  = (const float*)d_in[5];
    const float* wfc = (const float*)d_in[6];

    float* out  = (float*)d_out;
    float* attn = out + OUT_ELEMS;

    float *gq, *gk, *gv, *gctx, *gfc;
    __half* ge;
    cudaGetSymbolAddress((void**)&gq,   g_q);
    cudaGetSymbolAddress((void**)&gk,   g_k);
    cudaGetSymbolAddress((void**)&gv,   g_v);
    cudaGetSymbolAddress((void**)&gctx, g_ctx);
    cudaGetSymbolAddress((void**)&gfc,  g_fc);
    cudaGetSymbolAddress((void**)&ge,   g_e);

    dim3 gg(DM/128, MTOT/128);
    size_t gemm_smem = (size_t)4 * 128 * KPAD * sizeof(unsigned);
    cudaFuncSetAttribute(gemm_tf32, cudaFuncAttributeMaxDynamicSharedMemorySize, (int)gemm_smem);

    gemm_tf32<<<gg, 256, gemm_smem>>>(iq, wq, nullptr, gq, 0);
    gemm_tf32<<<gg, 256, gemm_smem>>>(ik, wk, nullptr, gk, 0);
    gemm_tf32<<<gg, 256, gemm_smem>>>(iv, wv, nullptr, gv, 0);

    size_t smem = (size_t)SM_ATT * sizeof(float);   // 107264 B
    cudaFuncSetAttribute(attn_kernel, cudaFuncAttributeMaxDynamicSharedMemorySize, (int)smem);
    attn_kernel<<<BATCH*NH*(SEQ/64), 256, smem>>>(gq, gk, gv, attn, gctx, ge);

    gemm_tf32<<<gg, 256, gemm_smem>>>(gctx, wfc, iq, gfc, 1);
    ln_kernel<<<MTOT, 256>>>(gfc, out);
}

// round 12
// speedup vs baseline: 1.4864x; 1.3748x over previous
#include <cuda_runtime.h>
#include <cuda_fp16.h>
#include <math.h>

#define BATCH 4
#define SEQ   2048
#define DM    1024
#define NH    16
#define DH    64
#define MTOT  (BATCH*SEQ)
#define OUT_ELEMS ((size_t)MTOT*DM)

__device__ float g_q[BATCH*NH*SEQ*DH];   // [b,h,s,d] raw fp32
__device__ float g_k[BATCH*NH*SEQ*DH];   // [b,h,s,d] tf32-quantized values
__device__ float g_v[BATCH*NH*SEQ*DH];   // [b,h,s,d] tf32-quantized values
__device__ float g_ctx[MTOT*DM];
__device__ float g_fc[MTOT*DM];
__device__ __half g_e[(size_t)BATCH*NH*SEQ*SEQ];   // unnormalized exp(s)/16

__device__ __forceinline__ unsigned f2tf(float x) {
    unsigned r;
    asm("cvt.rna.tf32.f32 %0, %1;" : "=r"(r) : "f"(x));
    return r;
}

__device__ __forceinline__ void mma8(float* c, const unsigned* a, unsigned b0, unsigned b1) {
    asm volatile(
        "mma.sync.aligned.m16n8k8.row.col.f32.tf32.tf32.f32 "
        "{%0,%1,%2,%3},{%4,%5,%6,%7},{%8,%9},{%0,%1,%2,%3};"
        : "+f"(c[0]), "+f"(c[1]), "+f"(c[2]), "+f"(c[3])
        : "r"(a[0]), "r"(a[1]), "r"(a[2]), "r"(a[3]), "r"(b0), "r"(b1));
}

__device__ __forceinline__ void cpasync16(unsigned saddr, const void* g) {
    asm volatile("cp.async.cg.shared.global [%0], [%1], 16;" :: "r"(saddr), "l"(g));
}
__device__ __forceinline__ void cpasync_commit() {
    asm volatile("cp.async.commit_group;");
}
__device__ __forceinline__ void cpasync_wait0() {
    asm volatile("cp.async.wait_group 0;");
}

// ---------------------------------------------------------------------------
// Dense GEMM: C = X[M,K] @ W[N,K]^T, tf32 mma, CTA 128x128, BK=16,
// double-buffered smem with register prefetch.
// mode 0: scatter to [B,H,S,Dh]; mode 1: +residual row-major;
// mode 3: scatter to [B,H,S,Dh] with rna-tf32 quantization (K, V).
// ---------------------------------------------------------------------------
#define KPAD 20

__global__ void __launch_bounds__(256, 2)
gemm_tf32(const float* __restrict__ X, const float* __restrict__ W,
          const float* __restrict__ resid, float* __restrict__ Y, int mode)
{
    extern __shared__ unsigned gsm[];
    unsigned (*As)[128][KPAD] = (unsigned(*)[128][KPAD])gsm;
    unsigned (*Bs)[128][KPAD] = (unsigned(*)[128][KPAD])(gsm + 2*128*KPAD);

    const int tid  = threadIdx.x;
    const int lane = tid & 31;
    const int warp = tid >> 5;
    const int warpM = warp >> 1;
    const int warpN = warp & 1;
    const int gid = lane >> 2;
    const int tig = lane & 3;

    const int ms = blockIdx.y * 128;
    const int ns = blockIdx.x * 128;
    const int lr = tid >> 2;
    const int lc = (tid & 3) * 4;

    float acc[2][8][4];
#pragma unroll
    for (int mt = 0; mt < 2; mt++)
#pragma unroll
        for (int nt = 0; nt < 8; nt++)
#pragma unroll
            for (int i = 0; i < 4; i++) acc[mt][nt][i] = 0.f;

    float4 px[2], pw[2];
#pragma unroll
    for (int h = 0; h < 2; h++) {
        int r = lr + h * 64;
        px[h] = *(const float4*)&X[(size_t)(ms + r) * DM + lc];
        pw[h] = *(const float4*)&W[(size_t)(ns + r) * DM + lc];
    }
#pragma unroll
    for (int h = 0; h < 2; h++) {
        int r = lr + h * 64;
        As[0][r][lc+0] = f2tf(px[h].x); As[0][r][lc+1] = f2tf(px[h].y);
        As[0][r][lc+2] = f2tf(px[h].z); As[0][r][lc+3] = f2tf(px[h].w);
        Bs[0][r][lc+0] = f2tf(pw[h].x); Bs[0][r][lc+1] = f2tf(pw[h].y);
        Bs[0][r][lc+2] = f2tf(pw[h].z); Bs[0][r][lc+3] = f2tf(pw[h].w);
    }
    __syncthreads();

    int buf = 0;
    for (int k0 = 0; k0 < DM; k0 += 16, buf ^= 1) {
        float4 nx[2], nw[2];
        const bool more = (k0 + 16 < DM);
        if (more) {
#pragma unroll
            for (int h = 0; h < 2; h++) {
                int r = lr + h * 64;
                nx[h] = *(const float4*)&X[(size_t)(ms + r) * DM + k0 + 16 + lc];
                nw[h] = *(const float4*)&W[(size_t)(ns + r) * DM + k0 + 16 + lc];
            }
        }

#pragma unroll
        for (int ks = 0; ks < 2; ks++) {
            const int kc = ks * 8 + tig;
            unsigned a[2][4];
#pragma unroll
            for (int mt = 0; mt < 2; mt++) {
                int base = warpM * 32 + mt * 16;
                a[mt][0] = As[buf][base + gid][kc];
                a[mt][1] = As[buf][base + gid + 8][kc];
                a[mt][2] = As[buf][base + gid][kc + 4];
                a[mt][3] = As[buf][base + gid + 8][kc + 4];
            }
#pragma unroll
            for (int nt = 0; nt < 8; nt++) {
                int cb = warpN * 64 + nt * 8 + gid;
                unsigned b0 = Bs[buf][cb][kc];
                unsigned b1 = Bs[buf][cb][kc + 4];
                mma8(acc[0][nt], a[0], b0, b1);
                mma8(acc[1][nt], a[1], b0, b1);
            }
        }

        if (more) {
            int nb = buf ^ 1;
#pragma unroll
            for (int h = 0; h < 2; h++) {
                int r = lr + h * 64;
                As[nb][r][lc+0] = f2tf(nx[h].x); As[nb][r][lc+1] = f2tf(nx[h].y);
                As[nb][r][lc+2] = f2tf(nx[h].z); As[nb][r][lc+3] = f2tf(nx[h].w);
                Bs[nb][r][lc+0] = f2tf(nw[h].x); Bs[nb][r][lc+1] = f2tf(nw[h].y);
                Bs[nb][r][lc+2] = f2tf(nw[h].z); Bs[nb][r][lc+3] = f2tf(nw[h].w);
            }
        }
        __syncthreads();
    }

#pragma unroll
    for (int mt = 0; mt < 2; mt++) {
#pragma unroll
        for (int nt = 0; nt < 8; nt++) {
#pragma unroll
            for (int i = 0; i < 4; i++) {
                int m = ms + warpM * 32 + mt * 16 + gid + (i >> 1) * 8;
                int n = ns + warpN * 64 + nt * 8 + tig * 2 + (i & 1);
                float v = acc[mt][nt][i];
                if (mode == 0) {
                    int b_ = m >> 11, s_ = m & 2047;
                    int h = n >> 6, dh = n & 63;
                    Y[(((size_t)(b_*NH + h))*SEQ + s_)*DH + dh] = v;
                } else if (mode == 3) {
                    int b_ = m >> 11, s_ = m & 2047;
                    int h = n >> 6, dh = n & 63;
                    Y[(((size_t)(b_*NH + h))*SEQ + s_)*DH + dh] = __uint_as_float(f2tf(v));
                } else {
                    Y[(size_t)m * DM + n] = v + resid[(size_t)m * DM + n];
                }
            }
        }
    }
}

// ---------------------------------------------------------------------------
// Flash-style attention. CTA = (b,h, 64 q rows), 256 thr, 8 warps =
// 4 q-groups x 2 key-slices. K/V gmem values are pre-quantized to tf32 ->
// raw cp.async staging is exact. Double-buffered 64-key tiles, one sync/tile.
// QK with split hi/lo accumulators (2x ILP). e stored tf32 in smem for PV,
// dumped fp16/16 coalesced to g_e; end sweep normalizes into attn_out.
// ---------------------------------------------------------------------------
#define AKT   64
#define NTIL  (SEQ/AKT)                    // 32
#define SKSTR 68
#define SVSTR 72
#define SESTR 36
#define KBUF  (AKT*SKSTR)                  // 4352
#define VBUF  (AKT*SVSTR)                  // 4608
#define SM_K   0
#define SM_V   (2*KBUF)                    // 8704
#define SM_E   (SM_V + 2*VBUF)             // 17920
#define SM_SUM (SM_E + 8*16*SESTR)         // 22528
#define SM_INV (SM_SUM + 128)              // 22656
#define SM_ATT (SM_INV + 64)               // 22720 floats = 90880 B

__global__ void __launch_bounds__(256, 2)
attn_kernel(const float* __restrict__ gq, const float* __restrict__ gk,
            const float* __restrict__ gv, float* __restrict__ attn_out,
            float* __restrict__ ctx, __half* __restrict__ gE)
{
    extern __shared__ float sm[];
    float* sE   = sm + SM_E;
    float* sSum = sm + SM_SUM;
    float* sInv = sm + SM_INV;

    const int tid  = threadIdx.x;
    const int lane = tid & 31;
    const int w    = tid >> 5;       // 0..7
    const int gid  = lane >> 2;      // 0..7
    const int tig  = lane & 3;       // 0..3
    const int qg   = w >> 1;         // 0..3
    const int ns   = w & 1;          // 0..1

    const int bid = blockIdx.x;
    const int qt  = bid & 31;
    const int bh  = bid >> 5;
    const int q0  = qt * 64;

    const float* Qb = gq + (size_t)bh * SEQ * DH;
    const float* Kb = gk + (size_t)bh * SEQ * DH;
    const float* Vb = gv + (size_t)bh * SEQ * DH;

    const unsigned sbase = (unsigned)__cvta_generic_to_shared(sm);
    float* sEw = sE + w * 16 * SESTR;

    // stage helper indices (per thread: 4 K + 4 V cp.asyncs per tile)
    const int str = tid >> 4;            // row sub 0..15
    const int stc = (tid & 15) << 2;     // col 0..60 step 4

    // ---- prologue: stage tile 0 ----
#pragma unroll
    for (int i = 0; i < 4; i++) {
        int r = str + i * 16;
        cpasync16(sbase + (SM_K + r*SKSTR + stc)*4, Kb + (size_t)r*DH + stc);
        cpasync16(sbase + (SM_V + r*SVSTR + stc)*4, Vb + (size_t)r*DH + stc);
    }
    cpasync_commit();

    // ---- Q fragments (hi/lo tf32), scale folded ----
    unsigned qhi[8][4], qlo[8][4];
    {
        const float* Qr0 = Qb + (size_t)(q0 + qg*16 + gid) * DH;
        const float* Qr1 = Qr0 + (size_t)8 * DH;
#pragma unroll
        for (int kc = 0; kc < 8; kc++) {
            float v[4];
            v[0] = Qr0[kc*8 + tig]     * 0.125f;
            v[1] = Qr1[kc*8 + tig]     * 0.125f;
            v[2] = Qr0[kc*8 + tig + 4] * 0.125f;
            v[3] = Qr1[kc*8 + tig + 4] * 0.125f;
#pragma unroll
            for (int i = 0; i < 4; i++) {
                unsigned h = f2tf(v[i]);
                qhi[kc][i] = h;
                qlo[kc][i] = f2tf(v[i] - __uint_as_float(h));
            }
        }
    }

    float rsum0 = 0.f, rsum1 = 0.f;
    float acc2[8][4];
#pragma unroll
    for (int nd = 0; nd < 8; nd++)
#pragma unroll
        for (int i = 0; i < 4; i++) acc2[nd][i] = 0.f;

    // ================= main pass =================
    for (int t = 0; t < NTIL; t++) {
        const int buf = t & 1;
        const float* sKb = sm + SM_K + buf*KBUF;
        const float* sVb = sm + SM_V + buf*VBUF;

        cpasync_wait0();
        __syncthreads();

        if (t + 1 < NTIL) {
            const int nb = (t + 1) & 1;
            const float* Kn = Kb + (size_t)(t+1)*AKT*DH;
            const float* Vn = Vb + (size_t)(t+1)*AKT*DH;
#pragma unroll
            for (int i = 0; i < 4; i++) {
                int r = str + i * 16;
                cpasync16(sbase + (SM_K + nb*KBUF + r*SKSTR + stc)*4, Kn + (size_t)r*DH + stc);
                cpasync16(sbase + (SM_V + nb*VBUF + r*SVSTR + stc)*4, Vn + (size_t)r*DH + stc);
            }
            cpasync_commit();
        }

        // ---- QK + exp + e staging (warp-local), split hi/lo accumulators ----
#pragma unroll
        for (int n8 = 0; n8 < 4; n8++) {
            const int n0 = ns * 32 + n8 * 8;
            float ah[4] = {0.f, 0.f, 0.f, 0.f};
            float al[4] = {0.f, 0.f, 0.f, 0.f};
#pragma unroll
            for (int kc = 0; kc < 8; kc++) {
                unsigned b0 = __float_as_uint(sKb[(n0 + gid)*SKSTR + kc*8 + tig]);
                unsigned b1 = __float_as_uint(sKb[(n0 + gid)*SKSTR + kc*8 + tig + 4]);
                mma8(ah, qhi[kc], b0, b1);
                mma8(al, qlo[kc], b0, b1);
            }
            float a0 = __expf(ah[0] + al[0]);
            float a1 = __expf(ah[1] + al[1]);
            float a2 = __expf(ah[2] + al[2]);
            float a3 = __expf(ah[3] + al[3]);
            rsum0 += a0 + a1;
            rsum1 += a2 + a3;
            sEw[gid*SESTR + n8*8 + 2*tig]       = __uint_as_float(f2tf(a0));
            sEw[gid*SESTR + n8*8 + 2*tig + 1]   = __uint_as_float(f2tf(a1));
            sEw[(gid+8)*SESTR + n8*8 + 2*tig]   = __uint_as_float(f2tf(a2));
            sEw[(gid+8)*SESTR + n8*8 + 2*tig+1] = __uint_as_float(f2tf(a3));
        }
        __syncwarp();

        // ---- PV over this warp's 32 keys ----
#pragma unroll
        for (int k8 = 0; k8 < 4; k8++) {
            unsigned a[4];
            a[0] = __float_as_uint(sEw[gid*SESTR + k8*8 + tig]);
            a[1] = __float_as_uint(sEw[(gid+8)*SESTR + k8*8 + tig]);
            a[2] = __float_as_uint(sEw[gid*SESTR + k8*8 + tig + 4]);
            a[3] = __float_as_uint(sEw[(gid+8)*SESTR + k8*8 + tig + 4]);
            const int kr = ns * 32 + k8 * 8;
#pragma unroll
            for (int nd = 0; nd < 8; nd++) {
                unsigned b0 = __float_as_uint(sVb[(kr + tig)*SVSTR + nd*8 + gid]);
                unsigned b1 = __float_as_uint(sVb[(kr + tig + 4)*SVSTR + nd*8 + gid]);
                mma8(acc2[nd], a, b0, b1);
            }
        }

        // ---- e dump: sEw (16x32) -> gE fp16 (scaled 1/16), coalesced ----
        {
            const int r0 = lane >> 2;            // 0..7
            const int c8 = (lane & 3) * 8;       // 0,8,16,24
#pragma unroll
            for (int rg = 0; rg < 16; rg += 8) {
                const float* s = &sEw[(rg + r0)*SESTR + c8];
                float4 v0 = *(const float4*)&s[0];
                float4 v1 = *(const float4*)&s[4];
                __half2 h0 = __floats2half2_rn(v0.x*0.0625f, v0.y*0.0625f);
                __half2 h1 = __floats2half2_rn(v0.z*0.0625f, v0.w*0.0625f);
                __half2 h2 = __floats2half2_rn(v1.x*0.0625f, v1.y*0.0625f);
                __half2 h3 = __floats2half2_rn(v1.z*0.0625f, v1.w*0.0625f);
                uint4 pk;
                pk.x = *(const unsigned*)&h0;
                pk.y = *(const unsigned*)&h1;
                pk.z = *(const unsigned*)&h2;
                pk.w = *(const unsigned*)&h3;
                *(uint4*)&gE[((size_t)bh*SEQ + q0 + qg*16 + rg + r0)*SEQ
                             + t*AKT + ns*32 + c8] = pk;
            }
        }
    }

    // ---- row-sum reduction ----
    rsum0 += __shfl_xor_sync(0xffffffffu, rsum0, 1);
    rsum0 += __shfl_xor_sync(0xffffffffu, rsum0, 2);
    rsum1 += __shfl_xor_sync(0xffffffffu, rsum1, 1);
    rsum1 += __shfl_xor_sync(0xffffffffu, rsum1, 2);
    if (tig == 0) {
        sSum[w*16 + gid]     = rsum0;
        sSum[w*16 + gid + 8] = rsum1;
    }
    __syncthreads();
    if (tid < 64) {
        int qgq = tid >> 4, r = tid & 15;
        float s = sSum[(qgq*2)*16 + r] + sSum[(qgq*2 + 1)*16 + r];
        sInv[tid] = 1.f / s;
    }
    // ---- O partial stage into retired K/V buffer region (stride 68) ----
    {
        float* sOw = sm + w * 1088;    // 16*68 per warp, 8*1088 = 8704 floats
#pragma unroll
        for (int nd = 0; nd < 8; nd++) {
            sOw[gid*68 + nd*8 + 2*tig]       = acc2[nd][0];
            sOw[gid*68 + nd*8 + 2*tig + 1]   = acc2[nd][1];
            sOw[(gid+8)*68 + nd*8 + 2*tig]   = acc2[nd][2];
            sOw[(gid+8)*68 + nd*8 + 2*tig+1] = acc2[nd][3];
        }
    }
    __syncthreads();

    // ---- ctx write ----
    {
        const int b_ = bh >> 4, h = bh & 15;
#pragma unroll
        for (int i = 0; i < 16; i++) {
            int idx = tid + i * 256;             // 0..4095
            int q = idx >> 6, dh = idx & 63;
            int qgi = q >> 4, r = q & 15;
            float o = sm[(qgi*2)*1088 + r*68 + dh]
                    + sm[(qgi*2 + 1)*1088 + r*68 + dh];
            o *= sInv[q];
            ctx[((size_t)(b_*SEQ + q0 + q))*DM + h*DH + dh] = o;
        }
    }

    // ---- normalization sweep: p = e_fp16 * (inv*16) -> gmem attn ----
    {
        const uint4* src = (const uint4*)(gE + ((size_t)bh*SEQ + q0)*SEQ);
        float* dst = attn_out + ((size_t)bh*SEQ + q0)*SEQ;
#pragma unroll 4
        for (int i = tid; i < 64*SEQ/8; i += 256) {   // 16384 uint4
            float inv = sInv[i >> 8] * 16.f;           // (i*8) >> 11
            uint4 raw = src[i];
            float2 f0 = __half22float2(*(const __half2*)&raw.x);
            float2 f1 = __half22float2(*(const __half2*)&raw.y);
            float2 f2 = __half22float2(*(const __half2*)&raw.z);
            float2 f3 = __half22float2(*(const __half2*)&raw.w);
            float4 p0 = make_float4(f0.x*inv, f0.y*inv, f1.x*inv, f1.y*inv);
            float4 p1 = make_float4(f2.x*inv, f2.y*inv, f3.x*inv, f3.y*inv);
            *(float4*)&dst[i*8]     = p0;
            *(float4*)&dst[i*8 + 4] = p1;
        }
    }
}

// ---------------------------------------------------------------------------
__global__ void ln_kernel(const float* __restrict__ x, float* __restrict__ out)
{
    __shared__ float red[16];
    const int row = blockIdx.x, tid = threadIdx.x;
    const float* xr = x + (size_t)row * DM;
    float4 d = ((const float4*)xr)[tid];
    float s  = d.x + d.y + d.z + d.w;
    float sq = d.x*d.x + d.y*d.y + d.z*d.z + d.w*d.w;
#pragma unroll
    for (int o = 16; o; o >>= 1) {
        s  += __shfl_xor_sync(0xffffffffu, s,  o);
        sq += __shfl_xor_sync(0xffffffffu, sq, o);
    }
    int warp = tid >> 5, lane = tid & 31;
    if (lane == 0) { red[warp] = s; red[warp + 8] = sq; }
    __syncthreads();
    float st = 0.f, sqt = 0.f;
#pragma unroll
    for (int i = 0; i < 8; i++) { st += red[i]; sqt += red[8 + i]; }
    float mean = st * (1.f/1024.f);
    float var  = sqt * (1.f/1024.f) - mean * mean;
    float rstd = rsqrtf(var + 1e-5f);
    float4 o;
    o.x = (d.x - mean) * rstd; o.y = (d.y - mean) * rstd;
    o.z = (d.z - mean) * rstd; o.w = (d.w - mean) * rstd;
    ((float4*)(out + (size_t)row * DM))[tid] = o;
}

// ---------------------------------------------------------------------------
extern "C" void kernel_launch(void* const* d_in, const int* in_sizes, int n_in,
                              void* d_out, int out_size)
{
    const float* iq  = (const float*)d_in[0];
    const float* ik  = (const float*)d_in[1];
    const float* iv  = (const float*)d_in[2];
    const float* wq  = (const float*)d_in[3];
    const float* wk  = (const float*)d_in[4];
    const float* wv  = (const float*)d_in[5];
    const float* wfc = (const float*)d_in[6];

    float* out  = (float*)d_out;
    float* attn = out + OUT_ELEMS;

    float *gq, *gk, *gv, *gctx, *gfc;
    __half* ge;
    cudaGetSymbolAddress((void**)&gq,   g_q);
    cudaGetSymbolAddress((void**)&gk,   g_k);
    cudaGetSymbolAddress((void**)&gv,   g_v);
    cudaGetSymbolAddress((void**)&gctx, g_ctx);
    cudaGetSymbolAddress((void**)&gfc,  g_fc);
    cudaGetSymbolAddress((void**)&ge,   g_e);

    dim3 gg(DM/128, MTOT/128);
    size_t gemm_smem = (size_t)4 * 128 * KPAD * sizeof(unsigned);
    cudaFuncSetAttribute(gemm_tf32, cudaFuncAttributeMaxDynamicSharedMemorySize, (int)gemm_smem);

    gemm_tf32<<<gg, 256, gemm_smem>>>(iq, wq, nullptr, gq, 0);
    gemm_tf32<<<gg, 256, gemm_smem>>>(ik, wk, nullptr, gk, 3);
    gemm_tf32<<<gg, 256, gemm_smem>>>(iv, wv, nullptr, gv, 3);

    size_t smem = (size_t)SM_ATT * sizeof(float);   // 90880 B
    cudaFuncSetAttribute(attn_kernel, cudaFuncAttributeMaxDynamicSharedMemorySize, (int)smem);
    attn_kernel<<<BATCH*NH*(SEQ/64), 256, smem>>>(gq, gk, gv, attn, gctx, ge);

    gemm_tf32<<<gg, 256, gemm_smem>>>(gctx, wfc, iq, gfc, 1);
    ln_kernel<<<MTOT, 256>>>(gfc, out);
}